// round 3
// baseline (speedup 1.0000x reference)
#include <cuda_runtime.h>
#include <cstdint>

namespace {
constexpr int kB  = 1024;
constexpr int kL  = 26;
constexpr int kA  = 8192;
constexpr int kC1 = 256;
constexpr int kD  = 512;
constexpr int kE  = 1024;
constexpr int kM  = kB * kL;      // 26624
constexpr float kThr = 1e-6f;
}

// Scratch (allocation-free: __device__ globals)
__device__ float g_h1[(size_t)kM * kC1];        // 27.3 MB
__device__ float g_h2[(size_t)kM * kD];         // 54.5 MB
__device__ float g_gi[(size_t)kM * 3 * kD];     // 163.6 MB
__device__ float g_gh[(size_t)kB * 3 * kD];     // 6.3 MB
__device__ float g_hA[(size_t)kB * kD];
__device__ float g_hB[(size_t)kB * kD];

__device__ __forceinline__ uint32_t f2tf32(float f) {
    uint32_t u;
    asm("cvt.rna.tf32.f32 %0, %1;" : "=r"(u) : "f"(f));
    return u;
}

__device__ __forceinline__ void mma_tf32(float d[4], const uint32_t a[4], const uint32_t b[2]) {
    asm volatile(
        "mma.sync.aligned.m16n8k8.row.col.f32.tf32.tf32.f32 "
        "{%0,%1,%2,%3}, {%4,%5,%6,%7}, {%8,%9}, {%0,%1,%2,%3};"
        : "+f"(d[0]), "+f"(d[1]), "+f"(d[2]), "+f"(d[3])
        : "r"(a[0]), "r"(a[1]), "r"(a[2]), "r"(a[3]), "r"(b[0]), "r"(b[1]));
}

__device__ __forceinline__ void cp16(uint32_t saddr, const float* g) {
    asm volatile("cp.async.cg.shared.global [%0], [%1], 16;\n" :: "r"(saddr), "l"(g));
}

// C[M,N] = A[M,K] (row-major) * B[N,K]^T (+bias[n]) (optional threshold)
// All of M%128==0, N%128==0, K%16==0 hold for every call site.
template<bool THRESH>
__global__ void __launch_bounds__(128, 2)
gemm_tf32(const float* __restrict__ Ag, const float* __restrict__ Bg,
          const float* __restrict__ bias, float* __restrict__ Cg,
          int M, int N, int K)
{
    constexpr int BM = 128, BN = 128, BK = 16, LDSW = BK + 4;  // 20-float stride: conflict-free, 16B-aligned
    __shared__ float As[2][BM][LDSW];
    __shared__ float Bs[2][BN][LDSW];

    const int tid  = threadIdx.x;
    const int lane = tid & 31;
    const int warp = tid >> 5;
    const int wr = warp >> 1, wc = warp & 1;       // 2x2 warp grid, 64x64 warp tile
    const int grp = lane >> 2, tig = lane & 3;
    const int bm = blockIdx.y * BM;
    const int bn = blockIdx.x * BN;

    float acc[4][8][4];
#pragma unroll
    for (int i = 0; i < 4; i++)
#pragma unroll
        for (int j = 0; j < 8; j++)
#pragma unroll
            for (int c = 0; c < 4; c++) acc[i][j][c] = 0.f;

    // cp.async mapping: each thread loads 4x float4 for A and B per tile
    uint32_t sA0[4], sB0[4];
    const float *gA[4], *gB[4];
#pragma unroll
    for (int i = 0; i < 4; i++) {
        const int l  = tid + i * 128;
        const int r  = l >> 2;
        const int kk = (l & 3) * 4;
        sA0[i] = (uint32_t)__cvta_generic_to_shared(&As[0][r][kk]);
        sB0[i] = (uint32_t)__cvta_generic_to_shared(&Bs[0][r][kk]);
        gA[i] = Ag + (size_t)(bm + r) * K + kk;
        gB[i] = Bg + (size_t)(bn + r) * K + kk;
    }
    const uint32_t BUFB = BM * LDSW * 4;   // bytes per smem buffer

    const int NT = K / BK;

    // prologue: tile 0 -> buf 0
#pragma unroll
    for (int i = 0; i < 4; i++) { cp16(sA0[i], gA[i]); cp16(sB0[i], gB[i]); }
    asm volatile("cp.async.commit_group;\n");

    for (int kt = 0; kt < NT; kt++) {
        const int buf = kt & 1;
        if (kt + 1 < NT) {
            const uint32_t off = (uint32_t)(buf ^ 1) * BUFB;
            const int go = (kt + 1) * BK;
#pragma unroll
            for (int i = 0; i < 4; i++) { cp16(sA0[i] + off, gA[i] + go); cp16(sB0[i] + off, gB[i] + go); }
            asm volatile("cp.async.commit_group;\n");
            asm volatile("cp.async.wait_group 1;\n");
        } else {
            asm volatile("cp.async.wait_group 0;\n");
        }
        __syncthreads();

#pragma unroll
        for (int ks = 0; ks < 2; ks++) {
            const int k0 = ks * 8;
            uint32_t af[4][4], bf[8][2];
#pragma unroll
            for (int mi = 0; mi < 4; mi++) {
                const int r = wr * 64 + mi * 16 + grp;
                af[mi][0] = f2tf32(As[buf][r][k0 + tig]);
                af[mi][1] = f2tf32(As[buf][r + 8][k0 + tig]);
                af[mi][2] = f2tf32(As[buf][r][k0 + tig + 4]);
                af[mi][3] = f2tf32(As[buf][r + 8][k0 + tig + 4]);
            }
#pragma unroll
            for (int ni = 0; ni < 8; ni++) {
                const int c = wc * 64 + ni * 8 + grp;
                bf[ni][0] = f2tf32(Bs[buf][c][k0 + tig]);
                bf[ni][1] = f2tf32(Bs[buf][c][k0 + tig + 4]);
            }
#pragma unroll
            for (int mi = 0; mi < 4; mi++)
#pragma unroll
                for (int ni = 0; ni < 8; ni++)
                    mma_tf32(acc[mi][ni], af[mi], bf[ni]);
        }
        __syncthreads();
    }

    // epilogue: bias (+ optional threshold), float2 stores
#pragma unroll
    for (int mi = 0; mi < 4; mi++) {
        const int r0 = bm + wr * 64 + mi * 16 + grp;
#pragma unroll
        for (int ni = 0; ni < 8; ni++) {
            const int c0 = bn + wc * 64 + ni * 8 + tig * 2;
            const float b0 = bias[c0], b1 = bias[c0 + 1];
            float v00 = acc[mi][ni][0] + b0;
            float v01 = acc[mi][ni][1] + b1;
            float v10 = acc[mi][ni][2] + b0;
            float v11 = acc[mi][ni][3] + b1;
            if (THRESH) {
                v00 = (v00 > kThr) ? v00 : 0.f;
                v01 = (v01 > kThr) ? v01 : 0.f;
                v10 = (v10 > kThr) ? v10 : 0.f;
                v11 = (v11 > kThr) ? v11 : 0.f;
            }
            *(float2*)&Cg[(size_t)r0 * N + c0]       = make_float2(v00, v01);
            *(float2*)&Cg[(size_t)(r0 + 8) * N + c0] = make_float2(v10, v11);
        }
    }
}

// h_new = (1-z)*n + z*h_prev with r,z,n from gi (precomputed, all t) and gh (this t)
__global__ void gru_update(const float* __restrict__ gi, int t,
                           const float* __restrict__ gh,
                           const float* __restrict__ hprev,
                           float* __restrict__ hnew)
{
    const int idx = blockIdx.x * blockDim.x + threadIdx.x;   // 0 .. kB*kD-1
    const int b = idx / kD;
    const int j = idx - b * kD;
    const float* gir = gi + (size_t)(b * kL + t) * (3 * kD);
    const float* ghr = gh + (size_t)b * (3 * kD);
    const float ir = gir[j], iz = gir[kD + j], in_ = gir[2 * kD + j];
    const float hr = ghr[j], hz = ghr[kD + j], hn  = ghr[2 * kD + j];
    const float r = 1.f / (1.f + expf(-(ir + hr)));
    const float z = 1.f / (1.f + expf(-(iz + hz)));
    const float n = tanhf(in_ + r * hn);
    hnew[idx] = (1.f - z) * n + z * hprev[idx];
}

extern "C" void kernel_launch(void* const* d_in, const int* in_sizes, int n_in,
                              void* d_out, int out_size)
{
    (void)in_sizes; (void)n_in; (void)out_size;
    const float* x     = (const float*)d_in[0];
    const float* w1    = (const float*)d_in[1];
    const float* b1    = (const float*)d_in[2];
    const float* w2    = (const float*)d_in[3];
    const float* b2    = (const float*)d_in[4];
    const float* w_ih  = (const float*)d_in[5];
    const float* w_hh  = (const float*)d_in[6];
    const float* b_ih  = (const float*)d_in[7];
    const float* b_hh  = (const float*)d_in[8];
    const float* lin_w = (const float*)d_in[9];
    const float* lin_b = (const float*)d_in[10];
    float* out = (float*)d_out;

    float *h1, *h2, *gi, *gh, *hA, *hB;
    cudaGetSymbolAddress((void**)&h1, g_h1);
    cudaGetSymbolAddress((void**)&h2, g_h2);
    cudaGetSymbolAddress((void**)&gi, g_gi);
    cudaGetSymbolAddress((void**)&gh, g_gh);
    cudaGetSymbolAddress((void**)&hA, g_hA);
    cudaGetSymbolAddress((void**)&hB, g_hB);

    const dim3 blk(128);

    // conv1: [26624,8192] x [256,8192]^T, threshold
    gemm_tf32<true ><<<dim3(kC1 / 128,   kM / 128), blk>>>(x,  w1, b1, h1, kM, kC1,    kA);
    // conv2: [26624,256] x [512,256]^T, threshold
    gemm_tf32<true ><<<dim3(kD / 128,    kM / 128), blk>>>(h1, w2, b2, h2, kM, kD,     kC1);
    // gi (all timesteps batched): [26624,512] x [1536,512]^T
    gemm_tf32<false><<<dim3(3 * kD / 128, kM / 128), blk>>>(h2, w_ih, b_ih, gi, kM, 3 * kD, kD);

    // h0 = 0
    cudaMemsetAsync(hA, 0, (size_t)kB * kD * sizeof(float));

    float* cur = hA;
    float* nxt = hB;
    for (int t = 0; t < kL; t++) {
        // gh = h_prev @ w_hh^T + b_hh : [1024,512] x [1536,512]^T
        gemm_tf32<false><<<dim3(3 * kD / 128, kB / 128), blk>>>(cur, w_hh, b_hh, gh, kB, 3 * kD, kD);
        gru_update<<<(kB * kD) / 256, 256>>>(gi, t, gh, cur, nxt);
        float* tmp = cur; cur = nxt; nxt = tmp;
    }

    // out = h_last @ lin_w^T + lin_b : [1024,512] x [1024,512]^T
    gemm_tf32<false><<<dim3(kE / 128, kB / 128), blk>>>(cur, lin_w, lin_b, out, kB, kE, kD);
}

// round 4
// speedup vs baseline: 1.0376x; 1.0376x over previous
#include <cuda_runtime.h>
#include <cstdint>

namespace {
constexpr int kB  = 1024;
constexpr int kL  = 26;
constexpr int kA  = 8192;
constexpr int kC1 = 256;
constexpr int kD  = 512;
constexpr int kE  = 1024;
constexpr int kM  = kB * kL;      // 26624
constexpr float kThr = 1e-6f;
constexpr int HT_LD = 20;         // padded smem row stride (floats) for 16-wide k tiles
constexpr int WS_LD = 516;        // padded stride for resident w_hh slice (512 + 4)
}

// ---------------- scratch (allocation-free) ----------------
__device__ float g_h1[(size_t)kM * kC1];
__device__ float g_h2[(size_t)kM * kD];
__device__ float g_gi[(size_t)kM * 3 * kD];
__device__ float g_hA[(size_t)kB * kD];
__device__ float g_hB[(size_t)kB * kD];
__device__ float g_rw1[(size_t)kC1 * kA];
__device__ float g_rw2[(size_t)kD * kC1];
__device__ float g_rwih[(size_t)3 * kD * kD];
__device__ float g_rlin[(size_t)kE * kD];
__device__ unsigned g_bar_count = 0;
__device__ unsigned g_bar_gen   = 0;

// ---------------- helpers ----------------
__device__ __forceinline__ uint32_t f2tf32(float f) {
    uint32_t u;
    asm("cvt.rna.tf32.f32 %0, %1;" : "=r"(u) : "f"(f));
    return u;
}

__device__ __forceinline__ void mma_tf32(float d[4], const uint32_t a[4], const uint32_t b[2]) {
    asm volatile(
        "mma.sync.aligned.m16n8k8.row.col.f32.tf32.tf32.f32 "
        "{%0,%1,%2,%3}, {%4,%5,%6,%7}, {%8,%9}, {%0,%1,%2,%3};"
        : "+f"(d[0]), "+f"(d[1]), "+f"(d[2]), "+f"(d[3])
        : "r"(a[0]), "r"(a[1]), "r"(a[2]), "r"(a[3]), "r"(b[0]), "r"(b[1]));
}

__device__ __forceinline__ void cp16(uint32_t saddr, const float* g) {
    asm volatile("cp.async.cg.shared.global [%0], [%1], 16;\n" :: "r"(saddr), "l"(g));
}

__device__ __forceinline__ float sigm(float x)  { return 1.f / (1.f + __expf(-x)); }
__device__ __forceinline__ float tanhq(float x) { return 1.f - 2.f / (1.f + __expf(2.f * x)); }

// ---------------- pre-round weights to tf32 ----------------
__global__ void round_tf32(const float* __restrict__ in, float* __restrict__ out, int n4) {
    int i = blockIdx.x * blockDim.x + threadIdx.x;
    if (i < n4) {
        float4 v = ((const float4*)in)[i];
        v.x = __uint_as_float(f2tf32(v.x));
        v.y = __uint_as_float(f2tf32(v.y));
        v.z = __uint_as_float(f2tf32(v.z));
        v.w = __uint_as_float(f2tf32(v.w));
        ((float4*)out)[i] = v;
    }
}

// ---------------- GEMM v2 ----------------
// C[M,N] = A[M,K] * B[N,K]^T + bias.  B pre-rounded to tf32. 128x128 CTA tile,
// 256 threads (4x2 warps, 32x64 warp tile), 3-stage cp.async pipeline, tile loop.
template<bool THRESH, bool CVT_A, bool ROUND_OUT>
__global__ void __launch_bounds__(256, 2)
gemm2(const float* __restrict__ Ag, const float* __restrict__ Bg,
      const float* __restrict__ bias, float* __restrict__ Cg,
      int M, int N, int K, int ntiles, int tn)
{
    extern __shared__ float sm[];
    constexpr int AS = 128 * HT_LD;   // floats per A stage
    constexpr int SS = 2 * AS;        // floats per (A+B) stage
    const int tid  = threadIdx.x;
    const int lane = tid & 31, warp = tid >> 5;
    const int wr = warp >> 1, wc = warp & 1;
    const int grp = lane >> 2, tig = lane & 3;
    const int NT = K >> 4;
    const uint32_t smb = (uint32_t)__cvta_generic_to_shared(sm);

    int lr[2], lk[2];
#pragma unroll
    for (int i = 0; i < 2; i++) { int l = tid + i * 256; lr[i] = l >> 2; lk[i] = (l & 3) << 2; }

    for (int tile = blockIdx.x; tile < ntiles; tile += gridDim.x) {
        const int bm = (tile / tn) << 7;
        const int bn = (tile % tn) << 7;
        const float* Ab = Ag + (size_t)bm * K;
        const float* Bb = Bg + (size_t)bn * K;

        auto issue = [&](int kt, int st) {
            const int go = kt << 4;
#pragma unroll
            for (int i = 0; i < 2; i++) {
                uint32_t sa = smb + (uint32_t)(st * SS + lr[i] * HT_LD + lk[i]) * 4u;
                cp16(sa,           Ab + (size_t)lr[i] * K + go + lk[i]);
                cp16(sa + AS * 4u, Bb + (size_t)lr[i] * K + go + lk[i]);
            }
        };

        float acc[2][8][4];
#pragma unroll
        for (int a = 0; a < 2; a++)
#pragma unroll
            for (int b = 0; b < 8; b++)
#pragma unroll
                for (int c = 0; c < 4; c++) acc[a][b][c] = 0.f;

        issue(0, 0); asm volatile("cp.async.commit_group;\n");
        issue(1, 1); asm volatile("cp.async.commit_group;\n");

        for (int kt = 0; kt < NT; kt++) {
            if (kt + 2 < NT) issue(kt + 2, (kt + 2) % 3);
            asm volatile("cp.async.commit_group;\n");
            asm volatile("cp.async.wait_group 2;\n");
            __syncthreads();
            const float* As = sm + (kt % 3) * SS;
            const float* Bs = As + AS;
#pragma unroll
            for (int ks = 0; ks < 2; ks++) {
                const int k0 = ks * 8;
                uint32_t af[2][4], bf[8][2];
#pragma unroll
                for (int mi = 0; mi < 2; mi++) {
                    const int r = wr * 32 + mi * 16 + grp;
                    float a0 = As[r * HT_LD + k0 + tig];
                    float a1 = As[(r + 8) * HT_LD + k0 + tig];
                    float a2 = As[r * HT_LD + k0 + tig + 4];
                    float a3 = As[(r + 8) * HT_LD + k0 + tig + 4];
                    if (CVT_A) {
                        af[mi][0] = f2tf32(a0); af[mi][1] = f2tf32(a1);
                        af[mi][2] = f2tf32(a2); af[mi][3] = f2tf32(a3);
                    } else {
                        af[mi][0] = __float_as_uint(a0); af[mi][1] = __float_as_uint(a1);
                        af[mi][2] = __float_as_uint(a2); af[mi][3] = __float_as_uint(a3);
                    }
                }
#pragma unroll
                for (int ni = 0; ni < 8; ni++) {
                    const int c = wc * 64 + ni * 8 + grp;
                    bf[ni][0] = __float_as_uint(Bs[c * HT_LD + k0 + tig]);
                    bf[ni][1] = __float_as_uint(Bs[c * HT_LD + k0 + tig + 4]);
                }
#pragma unroll
                for (int mi = 0; mi < 2; mi++)
#pragma unroll
                    for (int ni = 0; ni < 8; ni++)
                        mma_tf32(acc[mi][ni], af[mi], bf[ni]);
            }
            __syncthreads();
        }

#pragma unroll
        for (int mi = 0; mi < 2; mi++) {
            const int r0 = bm + wr * 32 + mi * 16 + grp;
#pragma unroll
            for (int ni = 0; ni < 8; ni++) {
                const int c0 = bn + wc * 64 + ni * 8 + tig * 2;
                const float b0 = bias[c0], b1 = bias[c0 + 1];
                float v00 = acc[mi][ni][0] + b0, v01 = acc[mi][ni][1] + b1;
                float v10 = acc[mi][ni][2] + b0, v11 = acc[mi][ni][3] + b1;
                if (THRESH) {
                    v00 = (v00 > kThr) ? v00 : 0.f;  v01 = (v01 > kThr) ? v01 : 0.f;
                    v10 = (v10 > kThr) ? v10 : 0.f;  v11 = (v11 > kThr) ? v11 : 0.f;
                }
                if (ROUND_OUT) {
                    v00 = __uint_as_float(f2tf32(v00)); v01 = __uint_as_float(f2tf32(v01));
                    v10 = __uint_as_float(f2tf32(v10)); v11 = __uint_as_float(f2tf32(v11));
                }
                *(float2*)&Cg[(size_t)r0 * N + c0]       = make_float2(v00, v01);
                *(float2*)&Cg[(size_t)(r0 + 8) * N + c0] = make_float2(v10, v11);
            }
        }
    }
}

// ---------------- grid barrier (all CTAs resident: grid=128 <= 148 SMs) ----------------
__device__ __forceinline__ void grid_barrier() {
    __syncthreads();
    if (threadIdx.x == 0) {
        unsigned gen = *((volatile unsigned*)&g_bar_gen);
        __threadfence();
        if (atomicAdd(&g_bar_count, 1u) == gridDim.x - 1) {
            atomicExch(&g_bar_count, 0u);
            __threadfence();
            atomicAdd(&g_bar_gen, 1u);
        } else {
            while (*((volatile unsigned*)&g_bar_gen) == gen) { __nanosleep(32); }
            __threadfence();
        }
    }
    __syncthreads();
}

// ---------------- persistent fused GRU ----------------
// grid = 128: blockIdx = mt*16 + jc.  CTA owns batch rows [mt*128, +128) and
// gate columns [jc*32, +32).  Its 96-row w_hh slice (r/z/n sections) lives in
// smem for all 26 steps.  One grid barrier per step; ping-pong h in global.
__global__ void __launch_bounds__(256, 1)
gru_persistent(const float* __restrict__ gi, const float* __restrict__ w_hh,
               const float* __restrict__ b_hh,
               float* __restrict__ hA, float* __restrict__ hB)
{
    extern __shared__ float sm[];
    float* ws = sm;                       // [96][WS_LD]
    float* ht = sm + 96 * WS_LD;          // 3 stages x [128][HT_LD]
    constexpr int HTS = 128 * HT_LD;

    const int tid  = threadIdx.x;
    const int lane = tid & 31, warp = tid >> 5;
    const int grp = lane >> 2, tig = lane & 3;
    const int mt = blockIdx.x >> 4;
    const int jc = blockIdx.x & 15;
    const int m0 = mt * 128, j0 = jc * 32;

    // preload + round resident w_hh slice: ws row (g*32+c) <- w_hh row (g*512 + j0 + c)
    for (int i4 = tid; i4 < 96 * 128; i4 += 256) {
        const int row = i4 >> 7, k4 = (i4 & 127) << 2;
        const int g = row >> 5, c = row & 31;
        float4 v = *(const float4*)(w_hh + (size_t)(g * kD + j0 + c) * kD + k4);
        v.x = __uint_as_float(f2tf32(v.x));
        v.y = __uint_as_float(f2tf32(v.y));
        v.z = __uint_as_float(f2tf32(v.z));
        v.w = __uint_as_float(f2tf32(v.w));
        *(float4*)(ws + row * WS_LD + k4) = v;
    }

    // b_hh cached in regs: bf index ni -> gate (ni>>2), col j0 + (ni&3)*8 + tig*2
    float bhh0[12], bhh1[12];
#pragma unroll
    for (int ni = 0; ni < 12; ni++) {
        const int g = ni >> 2, j = j0 + (ni & 3) * 8 + tig * 2;
        bhh0[ni] = b_hh[g * kD + j];
        bhh1[ni] = b_hh[g * kD + j + 1];
    }
    __syncthreads();

    int lr[2], lk[2];
#pragma unroll
    for (int i = 0; i < 2; i++) { int l = tid + i * 256; lr[i] = l >> 2; lk[i] = (l & 3) << 2; }
    const uint32_t smb_ht = (uint32_t)__cvta_generic_to_shared(ht);

    for (int t = 0; t < kL; t++) {
        float* src = (t & 1) ? hA : hB;
        float* dst = (t & 1) ? hB : hA;

        float acc[12][4];
#pragma unroll
        for (int a = 0; a < 12; a++)
#pragma unroll
            for (int c = 0; c < 4; c++) acc[a][c] = 0.f;

        if (t > 0) {
            const float* Ab = src + (size_t)m0 * kD;
            auto issue = [&](int kt, int st) {
                const int go = kt << 4;
#pragma unroll
                for (int i = 0; i < 2; i++) {
                    uint32_t sa = smb_ht + (uint32_t)(st * HTS + lr[i] * HT_LD + lk[i]) * 4u;
                    cp16(sa, Ab + (size_t)lr[i] * kD + go + lk[i]);
                }
            };
            issue(0, 0); asm volatile("cp.async.commit_group;\n");
            issue(1, 1); asm volatile("cp.async.commit_group;\n");
            for (int kt = 0; kt < 32; kt++) {
                if (kt + 2 < 32) issue(kt + 2, (kt + 2) % 3);
                asm volatile("cp.async.commit_group;\n");
                asm volatile("cp.async.wait_group 2;\n");
                __syncthreads();
                const float* As = ht + (kt % 3) * HTS;
#pragma unroll
                for (int ks = 0; ks < 2; ks++) {
                    const int k0 = ks * 8, kk = (kt << 4) + k0;
                    uint32_t af[4], bf[12][2];
                    const int r = warp * 16 + grp;
                    af[0] = __float_as_uint(As[r * HT_LD + k0 + tig]);
                    af[1] = __float_as_uint(As[(r + 8) * HT_LD + k0 + tig]);
                    af[2] = __float_as_uint(As[r * HT_LD + k0 + tig + 4]);
                    af[3] = __float_as_uint(As[(r + 8) * HT_LD + k0 + tig + 4]);
#pragma unroll
                    for (int ni = 0; ni < 12; ni++) {
                        const int c = ni * 8 + grp;
                        bf[ni][0] = __float_as_uint(ws[c * WS_LD + kk + tig]);
                        bf[ni][1] = __float_as_uint(ws[c * WS_LD + kk + tig + 4]);
                    }
#pragma unroll
                    for (int ni = 0; ni < 12; ni++)
                        mma_tf32(acc[ni], af, bf[ni]);
                }
                __syncthreads();
            }
        }

        // fused gate update: acc[q]=gh_r, acc[q+4]=gh_z, acc[q+8]=gh_n
#pragma unroll
        for (int q = 0; q < 4; q++) {
#pragma unroll
            for (int s = 0; s < 2; s++) {
                const int b  = m0 + warp * 16 + grp + s * 8;
                const int jj = j0 + q * 8 + tig * 2;
                const float* gib = gi + ((size_t)b * kL + t) * (3 * kD);
                const float2 gr = *(const float2*)(gib + jj);
                const float2 gz = *(const float2*)(gib + kD + jj);
                const float2 gn = *(const float2*)(gib + 2 * kD + jj);
                float2 hp = make_float2(0.f, 0.f);
                if (t > 0) hp = *(const float2*)(src + (size_t)b * kD + jj);
                const float r0 = sigm(gr.x + acc[q][2 * s]     + bhh0[q]);
                const float r1 = sigm(gr.y + acc[q][2 * s + 1] + bhh1[q]);
                const float z0 = sigm(gz.x + acc[q + 4][2 * s]     + bhh0[q + 4]);
                const float z1 = sigm(gz.y + acc[q + 4][2 * s + 1] + bhh1[q + 4]);
                const float n0 = tanhq(gn.x + r0 * (acc[q + 8][2 * s]     + bhh0[q + 8]));
                const float n1 = tanhq(gn.y + r1 * (acc[q + 8][2 * s + 1] + bhh1[q + 8]));
                float h0 = (1.f - z0) * n0 + z0 * hp.x;
                float h1 = (1.f - z1) * n1 + z1 * hp.y;
                h0 = __uint_as_float(f2tf32(h0));   // pre-round: GEMM consumers skip cvt
                h1 = __uint_as_float(f2tf32(h1));
                *(float2*)(dst + (size_t)b * kD + jj) = make_float2(h0, h1);
            }
        }
        if (t < kL - 1) grid_barrier();
    }
}

// ---------------- host ----------------
extern "C" void kernel_launch(void* const* d_in, const int* in_sizes, int n_in,
                              void* d_out, int out_size)
{
    (void)in_sizes; (void)n_in; (void)out_size;
    const float* x     = (const float*)d_in[0];
    const float* w1    = (const float*)d_in[1];
    const float* b1    = (const float*)d_in[2];
    const float* w2    = (const float*)d_in[3];
    const float* b2    = (const float*)d_in[4];
    const float* w_ih  = (const float*)d_in[5];
    const float* w_hh  = (const float*)d_in[6];
    const float* b_ih  = (const float*)d_in[7];
    const float* b_hh  = (const float*)d_in[8];
    const float* lin_w = (const float*)d_in[9];
    const float* lin_b = (const float*)d_in[10];
    float* out = (float*)d_out;

    float *h1, *h2, *gi, *hA, *hB, *rw1, *rw2, *rwih, *rlin;
    cudaGetSymbolAddress((void**)&h1,   g_h1);
    cudaGetSymbolAddress((void**)&h2,   g_h2);
    cudaGetSymbolAddress((void**)&gi,   g_gi);
    cudaGetSymbolAddress((void**)&hA,   g_hA);
    cudaGetSymbolAddress((void**)&hB,   g_hB);
    cudaGetSymbolAddress((void**)&rw1,  g_rw1);
    cudaGetSymbolAddress((void**)&rw2,  g_rw2);
    cudaGetSymbolAddress((void**)&rwih, g_rwih);
    cudaGetSymbolAddress((void**)&rlin, g_rlin);

    constexpr int GEMM_SMEM = 3 * 2 * 128 * HT_LD * 4;                 // 61440
    constexpr int GRU_SMEM  = (96 * WS_LD + 3 * 128 * HT_LD) * 4;      // 228864
    cudaFuncSetAttribute(gemm2<true,  true,  true >, cudaFuncAttributeMaxDynamicSharedMemorySize, GEMM_SMEM);
    cudaFuncSetAttribute(gemm2<true,  false, true >, cudaFuncAttributeMaxDynamicSharedMemorySize, GEMM_SMEM);
    cudaFuncSetAttribute(gemm2<false, false, false>, cudaFuncAttributeMaxDynamicSharedMemorySize, GEMM_SMEM);
    cudaFuncSetAttribute(gru_persistent,             cudaFuncAttributeMaxDynamicSharedMemorySize, GRU_SMEM);

    // pre-round weights to tf32 (idempotent numerics; removes in-loop cvt)
    round_tf32<<<(kC1 * kA / 4 + 255) / 256, 256>>>(w1,    rw1,  kC1 * kA / 4);
    round_tf32<<<(kD * kC1 / 4 + 255) / 256, 256>>>(w2,    rw2,  kD * kC1 / 4);
    round_tf32<<<(3 * kD * kD / 4 + 255) / 256, 256>>>(w_ih, rwih, 3 * kD * kD / 4);
    round_tf32<<<(kE * kD / 4 + 255) / 256, 256>>>(lin_w, rlin, kE * kD / 4);

    // conv1: [26624,8192] x [256,8192]^T  (cvt A=x in-kernel; round+thresh out)
    gemm2<true, true, true ><<<(kM / 128) * (kC1 / 128), 256, GEMM_SMEM>>>(
        x, rw1, b1, h1, kM, kC1, kA, (kM / 128) * (kC1 / 128), kC1 / 128);
    // conv2: [26624,256] x [512,256]^T
    gemm2<true, false, true ><<<(kM / 128) * (kD / 128), 256, GEMM_SMEM>>>(
        h1, rw2, b2, h2, kM, kD, kC1, (kM / 128) * (kD / 128), kD / 128);
    // gi (all timesteps): [26624,512] x [1536,512]^T
    gemm2<false, false, false><<<(kM / 128) * (3 * kD / 128), 256, GEMM_SMEM>>>(
        h2, rwih, b_ih, gi, kM, 3 * kD, kD, (kM / 128) * (3 * kD / 128), 3 * kD / 128);

    // fused persistent GRU: 26 steps, 1 launch.  kL even -> last write lands in hB.
    gru_persistent<<<128, 256, GRU_SMEM>>>(gi, w_hh, b_hh, hA, hB);

    // out = h_last @ lin_w^T + lin_b
    gemm2<false, false, false><<<(kB / 128) * (kE / 128), 256, GEMM_SMEM>>>(
        hB, rlin, lin_b, out, kB, kE, kD, (kB / 128) * (kE / 128), kE / 128);
}

// round 6
// speedup vs baseline: 1.1896x; 1.1464x over previous
#include <cuda_runtime.h>
#include <cstdint>

namespace {
constexpr int kB  = 1024;
constexpr int kL  = 26;
constexpr int kA  = 8192;
constexpr int kC1 = 256;
constexpr int kD  = 512;
constexpr int kE  = 1024;
constexpr int kM  = kB * kL;      // 26624
constexpr float kThr = 1e-6f;
constexpr int HT_LD = 20;         // padded smem row stride (floats); 20*4=80B, 16B-aligned rows
constexpr int WS_LD = 516;        // GRU resident w_hh stride; 516*4=2064B, 16B-aligned
}

// ---------------- scratch (allocation-free) ----------------
__device__ float g_h1[(size_t)kM * kC1];
__device__ float g_h2[(size_t)kM * kD];
__device__ float g_gi[(size_t)kM * 3 * kD];
__device__ float g_hA[(size_t)kB * kD];
__device__ float g_hB[(size_t)kB * kD];
__device__ float g_rw1[(size_t)kC1 * kA];
__device__ float g_rw2[(size_t)kD * kC1];
__device__ float g_rwih[(size_t)3 * kD * kD];
__device__ float g_rlin[(size_t)kE * kD];
__device__ unsigned g_bar_count = 0;
__device__ unsigned g_bar_gen   = 0;

// ---------------- helpers ----------------
__device__ __forceinline__ uint32_t f2tf32(float f) {
    uint32_t u;
    asm("cvt.rna.tf32.f32 %0, %1;" : "=r"(u) : "f"(f));
    return u;
}
__device__ __forceinline__ void mma_tf32(float d[4], const uint32_t a[4], const uint32_t b[2]) {
    asm volatile(
        "mma.sync.aligned.m16n8k8.row.col.f32.tf32.tf32.f32 "
        "{%0,%1,%2,%3}, {%4,%5,%6,%7}, {%8,%9}, {%0,%1,%2,%3};"
        : "+f"(d[0]), "+f"(d[1]), "+f"(d[2]), "+f"(d[3])
        : "r"(a[0]), "r"(a[1]), "r"(a[2]), "r"(a[3]), "r"(b[0]), "r"(b[1]));
}
__device__ __forceinline__ void cp16(uint32_t saddr, const float* g) {
    asm volatile("cp.async.cg.shared.global [%0], [%1], 16;\n" :: "r"(saddr), "l"(g));
}
__device__ __forceinline__ uint32_t smem_u32(const void* p) {
    uint32_t a;
    asm("{ .reg .u64 t; cvta.to.shared.u64 t, %1; cvt.u32.u64 %0, t; }" : "=r"(a) : "l"(p));
    return a;
}
// ldmatrix x4: four 8x8 b16 tiles == four 8x4 tf32 tiles; reg j of thread l holds
// tf32 element [row = l/4][col = l%4] of tile j  (exactly the mma.sync frag layout)
__device__ __forceinline__ void ldsm4(uint32_t r[4], uint32_t saddr) {
    asm volatile("ldmatrix.sync.aligned.m8n8.x4.shared.b16 {%0,%1,%2,%3}, [%4];"
        : "=r"(r[0]), "=r"(r[1]), "=r"(r[2]), "=r"(r[3]) : "r"(saddr));
}
__device__ __forceinline__ float sigm(float x)  { return 1.f / (1.f + __expf(-x)); }
__device__ __forceinline__ float tanhq(float x) { return 1.f - 2.f / (1.f + __expf(2.f * x)); }

// ---------------- pre-round weights to tf32 ----------------
__global__ void round_tf32(const float* __restrict__ in, float* __restrict__ out, int n4) {
    int i = blockIdx.x * blockDim.x + threadIdx.x;
    if (i < n4) {
        float4 v = ((const float4*)in)[i];
        v.x = __uint_as_float(f2tf32(v.x));
        v.y = __uint_as_float(f2tf32(v.y));
        v.z = __uint_as_float(f2tf32(v.z));
        v.w = __uint_as_float(f2tf32(v.w));
        ((float4*)out)[i] = v;
    }
}

// ---------------- GEMM v3: ldmatrix frags, 4-stage cp.async, 1 sync/k-tile ----
// C[M,N] = A[M,K] * B[N,K]^T + bias.  128x128 CTA tile, 256 threads,
// 4x2 warp grid (32x64 warp tiles).  bn varies fastest across blockIdx.
template<bool THRESH, bool CVT_A, bool ROUND_OUT>
__global__ void __launch_bounds__(256, 2)
gemm3(const float* __restrict__ Ag, const float* __restrict__ Bg,
      const float* __restrict__ bias, float* __restrict__ Cg,
      int M, int N, int K, int ntiles, int tn)
{
    extern __shared__ float sm[];
    constexpr int AS = 128 * HT_LD;   // floats per A stage
    constexpr int SS = 2 * AS;        // floats per (A+B) stage
    const int tid  = threadIdx.x;
    const int lane = tid & 31, warp = tid >> 5;
    const int wr = warp >> 1, wc = warp & 1;
    const int grp = lane >> 2, tig = lane & 3;
    const int sel = lane >> 3, rw = lane & 7;
    const int NT = K >> 4;
    const uint32_t smb = smem_u32(sm);

    // cp.async mapping: 2 16B chunks of A + 2 of B per thread per stage
    int lr[2], lk[2];
#pragma unroll
    for (int i = 0; i < 2; i++) { int l = tid + i * 256; lr[i] = l >> 2; lk[i] = (l & 3) << 2; }

    // ldmatrix base addresses (stage 0, k0 = 0)
    uint32_t adA[2], adB[4];
#pragma unroll
    for (int mi = 0; mi < 2; mi++) {
        const int row = wr * 32 + mi * 16 + ((sel & 1) << 3) + rw;
        const int kc  = (sel >> 1) << 2;
        adA[mi] = smb + (uint32_t)(row * HT_LD + kc) * 4u;
    }
#pragma unroll
    for (int p = 0; p < 4; p++) {
        const int row = wc * 64 + p * 16 + ((sel >> 1) << 3) + rw;
        const int kc  = (sel & 1) << 2;
        adB[p] = smb + (uint32_t)(AS + row * HT_LD + kc) * 4u;
    }

    for (int tile = blockIdx.x; tile < ntiles; tile += gridDim.x) {
        const int bm = (tile / tn) << 7;
        const int bn = (tile % tn) << 7;
        const float* Ab = Ag + (size_t)bm * K;
        const float* Bb = Bg + (size_t)bn * K;

        auto issue = [&](int kt) {
            const int st = kt & 3;
            const int go = kt << 4;
#pragma unroll
            for (int i = 0; i < 2; i++) {
                uint32_t sa = smb + (uint32_t)(st * SS + lr[i] * HT_LD + lk[i]) * 4u;
                cp16(sa,           Ab + (size_t)lr[i] * K + go + lk[i]);
                cp16(sa + AS * 4u, Bb + (size_t)lr[i] * K + go + lk[i]);
            }
            asm volatile("cp.async.commit_group;\n");
        };

        float acc[2][8][4];
#pragma unroll
        for (int a = 0; a < 2; a++)
#pragma unroll
            for (int b = 0; b < 8; b++)
#pragma unroll
                for (int c = 0; c < 4; c++) acc[a][b][c] = 0.f;

        issue(0); issue(1); issue(2);

        for (int kt = 0; kt < NT; kt++) {
            const int rem = NT - 1 - kt;
            if (rem >= 2)      asm volatile("cp.async.wait_group 2;\n");
            else if (rem == 1) asm volatile("cp.async.wait_group 1;\n");
            else               asm volatile("cp.async.wait_group 0;\n");
            __syncthreads();
            if (kt + 3 < NT) issue(kt + 3);

            const uint32_t stoff = (uint32_t)((kt & 3) * SS) * 4u;
#pragma unroll
            for (int ks = 0; ks < 2; ks++) {
                const uint32_t koff = stoff + (uint32_t)(ks * 8) * 4u;
                uint32_t af[2][4], bq[4][4];
#pragma unroll
                for (int mi = 0; mi < 2; mi++) {
                    ldsm4(af[mi], adA[mi] + koff);
                    if (CVT_A) {
#pragma unroll
                        for (int j = 0; j < 4; j++)
                            af[mi][j] = f2tf32(__uint_as_float(af[mi][j]));
                    }
                }
#pragma unroll
                for (int p = 0; p < 4; p++) ldsm4(bq[p], adB[p] + koff);
#pragma unroll
                for (int mi = 0; mi < 2; mi++)
#pragma unroll
                    for (int p = 0; p < 4; p++) {
                        mma_tf32(acc[mi][2 * p],     af[mi], &bq[p][0]);  // (n0..n0+7,  k0 / k0+4)
                        mma_tf32(acc[mi][2 * p + 1], af[mi], &bq[p][2]);  // (n0+8..+15, k0 / k0+4)
                    }
            }
        }
        __syncthreads();   // protect stages before next tile's prologue (no-op when loop runs once)

        // epilogue
#pragma unroll
        for (int mi = 0; mi < 2; mi++) {
            const int r0 = bm + wr * 32 + mi * 16 + grp;
#pragma unroll
            for (int ni = 0; ni < 8; ni++) {
                const int c0 = bn + wc * 64 + ni * 8 + tig * 2;
                const float b0 = bias[c0], b1 = bias[c0 + 1];
                float v00 = acc[mi][ni][0] + b0, v01 = acc[mi][ni][1] + b1;
                float v10 = acc[mi][ni][2] + b0, v11 = acc[mi][ni][3] + b1;
                if (THRESH) {
                    v00 = (v00 > kThr) ? v00 : 0.f;  v01 = (v01 > kThr) ? v01 : 0.f;
                    v10 = (v10 > kThr) ? v10 : 0.f;  v11 = (v11 > kThr) ? v11 : 0.f;
                }
                if (ROUND_OUT) {
                    v00 = __uint_as_float(f2tf32(v00)); v01 = __uint_as_float(f2tf32(v01));
                    v10 = __uint_as_float(f2tf32(v10)); v11 = __uint_as_float(f2tf32(v11));
                }
                *(float2*)&Cg[(size_t)r0 * N + c0]       = make_float2(v00, v01);
                *(float2*)&Cg[(size_t)(r0 + 8) * N + c0] = make_float2(v10, v11);
            }
        }
    }
}

// ---------------- grid barrier (grid=128 <= 148 SMs, 1 CTA/SM) ----------------
__device__ __forceinline__ void grid_barrier() {
    __syncthreads();
    if (threadIdx.x == 0) {
        unsigned gen = *((volatile unsigned*)&g_bar_gen);
        __threadfence();
        if (atomicAdd(&g_bar_count, 1u) == gridDim.x - 1) {
            atomicExch(&g_bar_count, 0u);
            __threadfence();
            atomicAdd(&g_bar_gen, 1u);
        } else {
            while (*((volatile unsigned*)&g_bar_gen) == gen) { __nanosleep(32); }
            __threadfence();
        }
    }
    __syncthreads();
}

// ---------------- persistent fused GRU (ldmatrix frags, 1 sync/k-tile) --------
__global__ void __launch_bounds__(256, 1)
gru_persistent(const float* __restrict__ gi, const float* __restrict__ w_hh,
               const float* __restrict__ b_hh,
               float* __restrict__ hA, float* __restrict__ hB)
{
    extern __shared__ float smf[];
    float* ws = smf;                      // [96][WS_LD] resident w_hh slice
    float* ht = smf + 96 * WS_LD;         // 3 stages x [128][HT_LD]
    constexpr int HTS = 128 * HT_LD;

    const int tid  = threadIdx.x;
    const int lane = tid & 31, warp = tid >> 5;
    const int grp = lane >> 2, tig = lane & 3;
    const int sel = lane >> 3, rw = lane & 7;
    const int mt = blockIdx.x >> 4;
    const int jc = blockIdx.x & 15;
    const int m0 = mt * 128, j0 = jc * 32;

    // preload + round resident w_hh slice: ws row (g*32+c) <- w_hh row (g*512 + j0 + c)
    for (int i4 = tid; i4 < 96 * 128; i4 += 256) {
        const int row = i4 >> 7, k4 = (i4 & 127) << 2;
        const int g = row >> 5, c = row & 31;
        float4 v = *(const float4*)(w_hh + (size_t)(g * kD + j0 + c) * kD + k4);
        v.x = __uint_as_float(f2tf32(v.x));
        v.y = __uint_as_float(f2tf32(v.y));
        v.z = __uint_as_float(f2tf32(v.z));
        v.w = __uint_as_float(f2tf32(v.w));
        *(float4*)(ws + row * WS_LD + k4) = v;
    }

    float bhh0[12], bhh1[12];
#pragma unroll
    for (int ni = 0; ni < 12; ni++) {
        const int g = ni >> 2, j = j0 + (ni & 3) * 8 + tig * 2;
        bhh0[ni] = b_hh[g * kD + j];
        bhh1[ni] = b_hh[g * kD + j + 1];
    }
    __syncthreads();

    int lr[2], lk[2];
#pragma unroll
    for (int i = 0; i < 2; i++) { int l = tid + i * 256; lr[i] = l >> 2; lk[i] = (l & 3) << 2; }
    const uint32_t smb_ht = smem_u32(ht);
    const uint32_t smb_ws = smem_u32(ws);

    // ldmatrix bases
    uint32_t adA, adB[6];
    {
        const int row = warp * 16 + ((sel & 1) << 3) + rw;
        adA = smb_ht + (uint32_t)(row * HT_LD + ((sel >> 1) << 2)) * 4u;
    }
#pragma unroll
    for (int p = 0; p < 6; p++) {
        const int row = p * 16 + ((sel >> 1) << 3) + rw;
        adB[p] = smb_ws + (uint32_t)(row * WS_LD + ((sel & 1) << 2)) * 4u;
    }

    for (int t = 0; t < kL; t++) {
        float* src = (t & 1) ? hA : hB;
        float* dst = (t & 1) ? hB : hA;

        float acc[12][4];
#pragma unroll
        for (int a = 0; a < 12; a++)
#pragma unroll
            for (int c = 0; c < 4; c++) acc[a][c] = 0.f;

        if (t > 0) {
            const float* Ab = src + (size_t)m0 * kD;
            auto issue = [&](int kt) {
                const int st = kt % 3;
                const int go = kt << 4;
#pragma unroll
                for (int i = 0; i < 2; i++) {
                    uint32_t sa = smb_ht + (uint32_t)(st * HTS + lr[i] * HT_LD + lk[i]) * 4u;
                    cp16(sa, Ab + (size_t)lr[i] * kD + go + lk[i]);
                }
                asm volatile("cp.async.commit_group;\n");
            };
            issue(0); issue(1);
            for (int kt = 0; kt < 32; kt++) {
                if (kt + 1 < 32) asm volatile("cp.async.wait_group 1;\n");
                else             asm volatile("cp.async.wait_group 0;\n");
                __syncthreads();
                if (kt + 2 < 32) issue(kt + 2);

                const uint32_t stoff = (uint32_t)((kt % 3) * HTS) * 4u;
#pragma unroll
                for (int ks = 0; ks < 2; ks++) {
                    const int kk = (kt << 4) + ks * 8;
                    uint32_t af[4], bq[6][4];
                    ldsm4(af, adA + stoff + (uint32_t)(ks * 8) * 4u);
#pragma unroll
                    for (int p = 0; p < 6; p++) ldsm4(bq[p], adB[p] + (uint32_t)kk * 4u);
#pragma unroll
                    for (int p = 0; p < 6; p++) {
                        mma_tf32(acc[2 * p],     af, &bq[p][0]);
                        mma_tf32(acc[2 * p + 1], af, &bq[p][2]);
                    }
                }
            }
            __syncthreads();
        }

        // fused gate update: acc[q]=gh_r, acc[q+4]=gh_z, acc[q+8]=gh_n
#pragma unroll
        for (int q = 0; q < 4; q++) {
#pragma unroll
            for (int s = 0; s < 2; s++) {
                const int b  = m0 + warp * 16 + grp + s * 8;
                const int jj = j0 + q * 8 + tig * 2;
                const float* gib = gi + ((size_t)b * kL + t) * (3 * kD);
                const float2 gr = *(const float2*)(gib + jj);
                const float2 gz = *(const float2*)(gib + kD + jj);
                const float2 gn = *(const float2*)(gib + 2 * kD + jj);
                float2 hp = make_float2(0.f, 0.f);
                if (t > 0) hp = *(const float2*)(src + (size_t)b * kD + jj);
                const float r0 = sigm(gr.x + acc[q][2 * s]     + bhh0[q]);
                const float r1 = sigm(gr.y + acc[q][2 * s + 1] + bhh1[q]);
                const float z0 = sigm(gz.x + acc[q + 4][2 * s]     + bhh0[q + 4]);
                const float z1 = sigm(gz.y + acc[q + 4][2 * s + 1] + bhh1[q + 4]);
                const float n0 = tanhq(gn.x + r0 * (acc[q + 8][2 * s]     + bhh0[q + 8]));
                const float n1 = tanhq(gn.y + r1 * (acc[q + 8][2 * s + 1] + bhh1[q + 8]));
                float h0 = (1.f - z0) * n0 + z0 * hp.x;
                float h1 = (1.f - z1) * n1 + z1 * hp.y;
                h0 = __uint_as_float(f2tf32(h0));
                h1 = __uint_as_float(f2tf32(h1));
                *(float2*)(dst + (size_t)b * kD + jj) = make_float2(h0, h1);
            }
        }
        if (t < kL - 1) grid_barrier();
    }
}

// ---------------- host ----------------
extern "C" void kernel_launch(void* const* d_in, const int* in_sizes, int n_in,
                              void* d_out, int out_size)
{
    (void)in_sizes; (void)n_in; (void)out_size;
    const float* x     = (const float*)d_in[0];
    const float* w1    = (const float*)d_in[1];
    const float* b1    = (const float*)d_in[2];
    const float* w2    = (const float*)d_in[3];
    const float* b2    = (const float*)d_in[4];
    const float* w_ih  = (const float*)d_in[5];
    const float* w_hh  = (const float*)d_in[6];
    const float* b_ih  = (const float*)d_in[7];
    const float* b_hh  = (const float*)d_in[8];
    const float* lin_w = (const float*)d_in[9];
    const float* lin_b = (const float*)d_in[10];
    float* out = (float*)d_out;

    float *h1, *h2, *gi, *hA, *hB, *rw1, *rw2, *rwih, *rlin;
    cudaGetSymbolAddress((void**)&h1,   g_h1);
    cudaGetSymbolAddress((void**)&h2,   g_h2);
    cudaGetSymbolAddress((void**)&gi,   g_gi);
    cudaGetSymbolAddress((void**)&hA,   g_hA);
    cudaGetSymbolAddress((void**)&hB,   g_hB);
    cudaGetSymbolAddress((void**)&rw1,  g_rw1);
    cudaGetSymbolAddress((void**)&rw2,  g_rw2);
    cudaGetSymbolAddress((void**)&rwih, g_rwih);
    cudaGetSymbolAddress((void**)&rlin, g_rlin);

    constexpr int GEMM_SMEM = 4 * 2 * 128 * HT_LD * 4;             // 81920
    constexpr int GRU_SMEM  = (96 * WS_LD + 3 * 128 * HT_LD) * 4;  // 228864
    cudaFuncSetAttribute(gemm3<true,  true,  true >, cudaFuncAttributeMaxDynamicSharedMemorySize, GEMM_SMEM);
    cudaFuncSetAttribute(gemm3<true,  false, true >, cudaFuncAttributeMaxDynamicSharedMemorySize, GEMM_SMEM);
    cudaFuncSetAttribute(gemm3<false, false, false>, cudaFuncAttributeMaxDynamicSharedMemorySize, GEMM_SMEM);
    cudaFuncSetAttribute(gru_persistent,             cudaFuncAttributeMaxDynamicSharedMemorySize, GRU_SMEM);

    // pre-round weights to tf32
    round_tf32<<<(kC1 * kA / 4 + 255) / 256, 256>>>(w1,    rw1,  kC1 * kA / 4);
    round_tf32<<<(kD * kC1 / 4 + 255) / 256, 256>>>(w2,    rw2,  kD * kC1 / 4);
    round_tf32<<<(3 * kD * kD / 4 + 255) / 256, 256>>>(w_ih, rwih, 3 * kD * kD / 4);
    round_tf32<<<(kE * kD / 4 + 255) / 256, 256>>>(lin_w, rlin, kE * kD / 4);

    const int tm = kM / 128;   // 208

    // conv1: [26624,8192] x [256,8192]^T  (cvt A in-kernel; threshold+round out)
    gemm3<true, true, true ><<<tm * 2, 256, GEMM_SMEM>>>(
        x, rw1, b1, h1, kM, kC1, kA, tm * 2, 2);
    // conv2: [26624,256] x [512,256]^T
    gemm3<true, false, true ><<<tm * 4, 256, GEMM_SMEM>>>(
        h1, rw2, b2, h2, kM, kD, kC1, tm * 4, 4);
    // gi (all timesteps): [26624,512] x [1536,512]^T
    gemm3<false, false, false><<<tm * 12, 256, GEMM_SMEM>>>(
        h2, rwih, b_ih, gi, kM, 3 * kD, kD, tm * 12, 12);

    // fused persistent GRU: 26 steps, 1 launch (kL even -> final h lands in hB)
    gru_persistent<<<128, 256, GRU_SMEM>>>(gi, w_hh, b_hh, hA, hB);

    // out = h_last @ lin_w^T + lin_b : [1024,512] x [1024,512]^T
    gemm3<false, false, false><<<8 * 8, 256, GEMM_SMEM>>>(
        hB, rlin, lin_b, out, kB, kE, kD, 8 * 8, 8);
}